// round 15
// baseline (speedup 1.0000x reference)
#include <cuda_runtime.h>
#include <cuda_fp16.h>
#include <math.h>

#define B_     2
#define S_     4096
#define HID_   2048
#define NH_    16
#define HD_    128
#define RATIO_ 4
#define NW_    1024
#define MS_    8192
#define QN_    2048
#define QKVN   2560   /* fused q(2048) | kv(256) | gate(256) */
#define KVGN   512

#define AQ  128
#define AK  64
#define QP  136

#define GBM 128
#define GBN 128
#define GBK 64
#define ASTR 72
#define BSTR 136
#define ASTAGE (GBM * ASTR)   /* 9216 halfs */
#define BSTAGE (GBK * BSTR)   /* 8704 halfs */
#define NSTAGE 3
#define HG_SMEM ((NSTAGE * (ASTAGE + BSTAGE)) * 2)   /* 107520 B */

/* attention smem: Q[AQ][QP] + K[2][AK][QP] + V[2][AK][QP] */
#define AT_SMEM ((AQ * QP + 4 * AK * QP) * 2)

// ---------------- scratch (static device allocations) ----------------
__device__ float g_kvg[(size_t)MS_ * KVGN];
__device__ float g_invfreq[32];

__device__ unsigned short g_h_hidden[(size_t)MS_ * HID_];
__device__ unsigned short g_h_wfused[(size_t)HID_ * QKVN];
__device__ unsigned short g_h_wo[(size_t)QN_ * HID_];
__device__ unsigned short g_h_attn[(size_t)MS_ * QN_];
__device__ unsigned short g_h_qrot[(size_t)MS_ * QN_];
__device__ unsigned short g_h_krot[(size_t)B_ * NW_ * HD_];
__device__ unsigned short g_h_v[(size_t)B_ * NW_ * HD_];

// ---------------- one-time inv-freq table ----------------
__global__ void init_invfreq_kernel()
{
    int i = threadIdx.x;
    if (i < 32) {
        g_invfreq[i] = (float)pow(10000.0, -(double)i / 32.0);
    }
}

// ---------------- fp32 -> fp16 (plain) ----------------
__global__ void f2h_kernel(const float4* __restrict__ in, __half2* __restrict__ out, int n4)
{
    int i = blockIdx.x * blockDim.x + threadIdx.x;
    if (i < n4) {
        float4 v = in[i];
        out[2 * i] = __floats2half2_rn(v.x, v.y);
        out[2 * i + 1] = __floats2half2_rn(v.z, v.w);
    }
}

// ---------------- pack wq|wkv|wgate -> fp16 [HID][QKVN] ----------------
__global__ void pack_w_kernel(const float* __restrict__ wq, const float* __restrict__ wkv,
                              const float* __restrict__ wgate, __half* __restrict__ dst)
{
    int idx = blockIdx.x * blockDim.x + threadIdx.x;
    if (idx >= HID_ * QKVN) return;
    int k = idx / QKVN;
    int n = idx % QKVN;
    float v;
    if (n < QN_) {
        v = wq[(size_t)k * QN_ + n];
    } else if (n < QN_ + 256) {
        v = wkv[(size_t)k * 256 + (n - QN_)];
    } else {
        v = wgate[(size_t)k * 256 + (n - QN_ - 256)];
    }
    dst[idx] = __float2half(v);
}

// ---------------- PTX helpers ----------------
__device__ __forceinline__ unsigned su32(const void* p)
{
    return (unsigned)__cvta_generic_to_shared(p);
}

__device__ __forceinline__ void cp16(void* dst, const void* src)
{
    unsigned d = su32(dst);
    asm volatile("cp.async.cg.shared.global [%0], [%1], 16;" :: "r"(d), "l"(src));
}

__device__ __forceinline__ void cp_commit()
{
    asm volatile("cp.async.commit_group;");
}

__device__ __forceinline__ void cp_wait1()
{
    asm volatile("cp.async.wait_group 1;");
}

__device__ __forceinline__ void cp_wait0()
{
    asm volatile("cp.async.wait_group 0;");
}

__device__ __forceinline__ void ldm_x4(unsigned* r, const void* p)
{
    unsigned a = su32(p);
    asm volatile("ldmatrix.sync.aligned.m8n8.x4.shared.b16 {%0,%1,%2,%3}, [%4];"
                 : "=r"(r[0]), "=r"(r[1]), "=r"(r[2]), "=r"(r[3]) : "r"(a));
}

__device__ __forceinline__ void ldm_x4_t(unsigned* r, const void* p)
{
    unsigned a = su32(p);
    asm volatile("ldmatrix.sync.aligned.m8n8.x4.trans.shared.b16 {%0,%1,%2,%3}, [%4];"
                 : "=r"(r[0]), "=r"(r[1]), "=r"(r[2]), "=r"(r[3]) : "r"(a));
}

__device__ __forceinline__ void mma16816(float* c, const unsigned* a, unsigned b0, unsigned b1)
{
    asm volatile("mma.sync.aligned.m16n8k16.row.col.f32.f16.f16.f32 "
                 "{%0,%1,%2,%3},{%4,%5,%6,%7},{%8,%9},{%0,%1,%2,%3};"
                 : "+f"(c[0]), "+f"(c[1]), "+f"(c[2]), "+f"(c[3])
                 : "r"(a[0]), "r"(a[1]), "r"(a[2]), "r"(a[3]), "r"(b0), "r"(b1));
}

// ---------------- GEMM mainloop: 256 threads, 8 warps of 32x64, GBK=64, 3-stage ----------------
struct GemmAcc {
    float a[2][8][4];
};

__device__ __forceinline__ void gemm_stage_load(
    const __half* __restrict__ A, const __half* __restrict__ Bm,
    int N, int K, int rowBase, int colBase, __half* As, __half* Bs, int tid)
{
#pragma unroll
    for (int u = 0; u < 4; u++) {
        int c = tid + u * 256;
        int ar = c >> 3, ac = (c & 7) * 8;
        cp16(&As[ar * ASTR + ac], A + (size_t)(rowBase + ar) * K + ac);
        int br = c >> 4, bc = (c & 15) * 8;
        cp16(&Bs[br * BSTR + bc], Bm + (size_t)br * N + colBase + bc);
    }
    cp_commit();
}

__device__ __forceinline__ void gemm_mainloop(
    const __half* __restrict__ A, const __half* __restrict__ Bm,
    int N, int K, int rowBase, int colBase, __half* hsm, GemmAcc& R)
{
    __half* As = hsm;
    __half* Bs = hsm + NSTAGE * ASTAGE;

    int tid = threadIdx.x;
    int lane = tid & 31;
    int wid = tid >> 5;
    int warpM = wid & 3;
    int warpN = wid >> 2;

#pragma unroll
    for (int i = 0; i < 2; i++)
#pragma unroll
        for (int j = 0; j < 8; j++)
#pragma unroll
            for (int c = 0; c < 4; c++)
                R.a[i][j][c] = 0.f;

    int T = K / GBK;

    // prologue: stages 0, 1
    gemm_stage_load(A, Bm, N, K, rowBase, colBase, &As[0], &Bs[0], tid);
    gemm_stage_load(A + GBK, Bm + (size_t)GBK * N, N, K, rowBase, colBase,
                    &As[ASTAGE], &Bs[BSTAGE], tid);

    for (int t = 0; t < T; t++) {
        if (t + 1 < T) {
            cp_wait1();      // drains stage t's group; stage t+1 may stay in flight
        } else {
            cp_wait0();
        }
        __syncthreads();

        if (t + 2 < T) {
            int so = (t + 2) % NSTAGE;
            gemm_stage_load(A + (size_t)(t + 2) * GBK, Bm + (size_t)(t + 2) * GBK * N,
                            N, K, rowBase, colBase, &As[so * ASTAGE], &Bs[so * BSTAGE], tid);
        }

        int s = t % NSTAGE;
        const __half* Asb = &As[s * ASTAGE];
        const __half* Bsb = &Bs[s * BSTAGE];
#pragma unroll
        for (int kk = 0; kk < GBK; kk += 16) {
            unsigned afr[2][4];
            unsigned bfr[4][4];
#pragma unroll
            for (int i = 0; i < 2; i++) {
                ldm_x4(afr[i], &Asb[(warpM * 32 + i * 16 + (lane & 15)) * ASTR + kk + (lane >> 4) * 8]);
            }
#pragma unroll
            for (int j = 0; j < 4; j++) {
                ldm_x4_t(bfr[j], &Bsb[(kk + ((lane >> 3) & 1) * 8 + (lane & 7)) * BSTR + warpN * 64 + j * 16 + (lane >> 4) * 8]);
            }
#pragma unroll
            for (int i = 0; i < 2; i++) {
#pragma unroll
                for (int j = 0; j < 4; j++) {
                    mma16816(R.a[i][2 * j], afr[i], bfr[j][0], bfr[j][1]);
                    mma16816(R.a[i][2 * j + 1], afr[i], bfr[j][2], bfr[j][3]);
                }
            }
        }
        __syncthreads();
    }
}

// ---------------- generic hgemm (fp32 C) for out-projection ----------------
__global__ __launch_bounds__(256, 2) void hgemm(
    const __half* __restrict__ A, const __half* __restrict__ Bm,
    float* __restrict__ C, int M, int N, int K)
{
    extern __shared__ __half hsm[];
    int lane = threadIdx.x & 31;
    int wid = threadIdx.x >> 5;
    int rowBase = blockIdx.y * GBM;
    int colBase = blockIdx.x * GBN;

    GemmAcc R;
    gemm_mainloop(A, Bm, N, K, rowBase, colBase, hsm, R);

    int r0 = rowBase + (wid & 3) * 32 + (lane >> 2);
    int c0 = colBase + (wid >> 2) * 64 + (lane & 3) * 2;
#pragma unroll
    for (int i = 0; i < 2; i++) {
#pragma unroll
        for (int j = 0; j < 8; j++) {
            float2* p0 = (float2*)&C[(size_t)(r0 + i * 16) * N + c0 + j * 8];
            p0[0] = make_float2(R.a[i][j][0], R.a[i][j][1]);
            float2* p1 = (float2*)&C[(size_t)(r0 + i * 16 + 8) * N + c0 + j * 8];
            p1[0] = make_float2(R.a[i][j][2], R.a[i][j][3]);
        }
    }
}

// ---------------- QKV hgemm with fused Q-RoPE epilogue ----------------
__device__ __forceinline__ void write_q_rope(int row, int col, float x, float y)
{
    int b = row >> 12;          // / S_
    int s = row & (S_ - 1);
    int h = col >> 7;           // / HD_
    int d = col & (HD_ - 1);
    int p = d >> 1;
    float y0 = x;
    float y1 = y;
    if (p >= 32) {
        float inv = g_invfreq[p - 32];
        float ang = (float)s * inv;
        float sn, cs;
        sincosf(ang, &sn, &cs);
        y0 = x * cs - y * sn;
        y1 = x * sn + y * cs;
    }
    const float scale = 0.08838834764831845f;
    __half2* dst = (__half2*)((__half*)g_h_qrot + (((size_t)b * NH_ + h) * S_ + s) * HD_ + d);
    dst[0] = __floats2half2_rn(y0 * scale, y1 * scale);
}

__global__ __launch_bounds__(256, 2) void hgemm_qkv(
    const __half* __restrict__ A, const __half* __restrict__ Bm, int K)
{
    extern __shared__ __half hsm[];
    int lane = threadIdx.x & 31;
    int wid = threadIdx.x >> 5;
    int rowBase = blockIdx.y * GBM;
    int colBase = blockIdx.x * GBN;

    GemmAcc R;
    gemm_mainloop(A, Bm, QKVN, K, rowBase, colBase, hsm, R);

    int r0 = rowBase + (wid & 3) * 32 + (lane >> 2);
    int c0 = colBase + (wid >> 2) * 64 + (lane & 3) * 2;

    if (colBase < QN_) {
#pragma unroll
        for (int i = 0; i < 2; i++) {
#pragma unroll
            for (int j = 0; j < 8; j++) {
                int col = c0 + j * 8;
                write_q_rope(r0 + i * 16, col, R.a[i][j][0], R.a[i][j][1]);
                write_q_rope(r0 + i * 16 + 8, col, R.a[i][j][2], R.a[i][j][3]);
            }
        }
    } else {
        int cb = c0 - QN_;
#pragma unroll
        for (int i = 0; i < 2; i++) {
#pragma unroll
            for (int j = 0; j < 8; j++) {
                float2* p0 = (float2*)&g_kvg[(size_t)(r0 + i * 16) * KVGN + cb + j * 8];
                p0[0] = make_float2(R.a[i][j][0], R.a[i][j][1]);
                float2* p1 = (float2*)&g_kvg[(size_t)(r0 + i * 16 + 8) * KVGN + cb + j * 8];
                p1[0] = make_float2(R.a[i][j][2], R.a[i][j][3]);
            }
        }
    }
}

// ---------------- overlap-pool + K-RoPE (reads slim kvg buffer) ----------------
__global__ void pool_kernel(const float* __restrict__ ape)
{
    int idx = blockIdx.x * blockDim.x + threadIdx.x;
    if (idx >= B_ * NW_ * 64) return;
    int p = idx & 63;
    int w = (idx >> 6) % NW_;
    int b = idx / (64 * NW_);
    int d0 = 2 * p;

    const float* base = g_kvg + (size_t)b * S_ * KVGN;

    float kvv[8][2];
    float gv[8][2];
#pragma unroll
    for (int j = 0; j < RATIO_; j++) {
        if (w > 0) {
            int t = (w - 1) * RATIO_ + j;
            const float* rowp = base + (size_t)t * KVGN;
            float2 kk = *(const float2*)&rowp[d0];
            float2 gg = *(const float2*)&rowp[256 + d0];
            float2 aa = *(const float2*)&ape[(size_t)j * 2 * HD_ + d0];
            kvv[j][0] = kk.x;
            kvv[j][1] = kk.y;
            gv[j][0] = gg.x + aa.x;
            gv[j][1] = gg.y + aa.y;
        } else {
            kvv[j][0] = 0.f;
            kvv[j][1] = 0.f;
            gv[j][0] = -1e30f;
            gv[j][1] = -1e30f;
        }
        int t2 = w * RATIO_ + j;
        const float* rowp2 = base + (size_t)t2 * KVGN;
        float2 kk2 = *(const float2*)&rowp2[HD_ + d0];
        float2 gg2 = *(const float2*)&rowp2[256 + HD_ + d0];
        float2 aa2 = *(const float2*)&ape[(size_t)j * 2 * HD_ + HD_ + d0];
        kvv[4 + j][0] = kk2.x;
        kvv[4 + j][1] = kk2.y;
        gv[4 + j][0] = gg2.x + aa2.x;
        gv[4 + j][1] = gg2.y + aa2.y;
    }

    float out2[2];
#pragma unroll
    for (int c = 0; c < 2; c++) {
        float m = -1e30f;
#pragma unroll
        for (int j = 0; j < 8; j++) m = fmaxf(m, gv[j][c]);
        float s = 0.f;
        float acc = 0.f;
#pragma unroll
        for (int j = 0; j < 8; j++) {
            float e = __expf(gv[j][c] - m);
            s += e;
            acc += e * kvv[j][c];
        }
        out2[c] = acc / s;
    }

    __half2* vp = (__half2*)((__half*)g_h_v + ((size_t)b * NW_ + w) * HD_ + d0);
    vp[0] = __floats2half2_rn(out2[0], out2[1]);

    float y0 = out2[0];
    float y1 = out2[1];
    if (p >= 32) {
        int i = p - 32;
        float inv = g_invfreq[i];
        float ang = (float)(w * RATIO_) * inv;
        float sn, cs;
        sincosf(ang, &sn, &cs);
        y0 = out2[0] * cs - out2[1] * sn;
        y1 = out2[0] * sn + out2[1] * cs;
    }
    __half2* kp = (__half2*)((__half*)g_h_krot + ((size_t)b * NW_ + w) * HD_ + d0);
    kp[0] = __floats2half2_rn(y0, y1);
}

// ---------------- tensor-core flash attention with sink, pipelined K/V ----------------
__global__ __launch_bounds__(256, 1) void attn_mma_kernel(const float* __restrict__ sinks)
{
    extern __shared__ __half smh[];
    __half* Qs = smh;                              // [AQ][QP]
    __half* Kb[2];
    __half* Vb[2];
    Kb[0] = Qs + AQ * QP;
    Vb[0] = Kb[0] + AK * QP;
    Kb[1] = Vb[0] + AK * QP;
    Vb[1] = Kb[1] + AK * QP;

    int tid = threadIdx.x;
    int lane = tid & 31;
    int wid = tid >> 5;
    int b = blockIdx.z;
    int h = blockIdx.y;
    int q0 = blockIdx.x * AQ;

    // load Q tile
    const __half* qsrc = (const __half*)g_h_qrot + (((size_t)b * NH_ + h) * S_ + q0) * HD_;
#pragma unroll
    for (int t = 0; t < 8; t++) {
        int lin = tid + t * 256;
        int row = lin >> 4;
        int c8 = (lin & 15) * 8;
        *(uint4*)&Qs[row * QP + c8] = *(const uint4*)&qsrc[(size_t)row * HD_ + c8];
    }
    __syncthreads();

    // preload Q fragments into registers (8 k16-chunks)
    unsigned qfr[8][4];
#pragma unroll
    for (int kk8 = 0; kk8 < 8; kk8++) {
        ldm_x4(qfr[kk8], &Qs[(wid * 16 + (lane & 15)) * QP + kk8 * 16 + (lane >> 4) * 8]);
    }

    float m0 = -1e30f, m1 = -1e30f;
    float l0 = 0.f, l1 = 0.f;
    float oacc[16][4];
#pragma unroll
    for (int j = 0; j < 16; j++)
#pragma unroll
        for (int c = 0; c < 4; c++)
            oacc[j][c] = 0.f;

    int kmax = (q0 + AQ - 4) >> 2;
    if (kmax > NW_ - 1) kmax = NW_ - 1;
    int nkt = kmax / AK + 1;

    const __half* kb = (const __half*)g_h_krot + (size_t)b * NW_ * HD_;
    const __half* vb = (const __half*)g_h_v + (size_t)b * NW_ * HD_;

    int row0 = q0 + wid * 16 + (lane >> 2);
    int row1 = row0 + 8;

    int ldrow = tid >> 4;          // 0..15
    int ldc8 = (tid & 15) * 8;

    // prologue: tile 0 -> buf 0
#pragma unroll
    for (int t = 0; t < 4; t++) {
        int row = ldrow + t * 16;
        cp16(&Kb[0][row * QP + ldc8], &kb[(size_t)row * HD_ + ldc8]);
        cp16(&Vb[0][row * QP + ldc8], &vb[(size_t)row * HD_ + ldc8]);
    }
    cp_commit();

    for (int kt = 0; kt < nkt; kt++) {
        cp_wait0();
        __syncthreads();

        if (kt + 1 < nkt) {
            int so = (kt + 1) & 1;
            const __half* kn = kb + (size_t)(kt + 1) * AK * HD_;
            const __half* vn = vb + (size_t)(kt + 1) * AK * HD_;
#pragma unroll
            for (int t = 0; t < 4; t++) {
                int row = ldrow + t * 16;
                cp16(&Kb[so][row * QP + ldc8], &kn[(size_t)row * HD_ + ldc8]);
                cp16(&Vb[so][row * QP + ldc8], &vn[(size_t)row * HD_ + ldc8]);
            }
            cp_commit();
        }

        const __half* Ks = Kb[kt & 1];
        const __half* Vs = Vb[kt & 1];

        // ---- S = Q K^T ----
        float sacc[8][4];
#pragma unroll
        for (int j = 0; j < 8; j++)
#pragma unroll
            for (int c = 0; c < 4; c++)
                sacc[j][c] = 0.f;

#pragma unroll
        for (int kk8 = 0; kk8 < 8; kk8++) {
#pragma unroll
            for (int j = 0; j < 4; j++) {
                unsigned bfr[4];
                ldm_x4(bfr, &Ks[(j * 16 + (lane >> 4) * 8 + (lane & 7)) * QP + kk8 * 16 + ((lane >> 3) & 1) * 8]);
                mma16816(sacc[2 * j], qfr[kk8], bfr[0], bfr[1]);
                mma16816(sacc[2 * j + 1], qfr[kk8], bfr[2], bfr[3]);
            }
        }

        // ---- mask ----
#pragma unroll
        for (int j = 0; j < 8; j++) {
            int kg = kt * AK + j * 8 + (lane & 3) * 2;
            if (row0 < 4 * kg + 3) sacc[j][0] = -1e30f;
            if (row0 < 4 * kg + 7) sacc[j][1] = -1e30f;
            if (row1 < 4 * kg + 3) sacc[j][2] = -1e30f;
            if (row1 < 4 * kg + 7) sacc[j][3] = -1e30f;
        }

        // ---- online softmax ----
        float mx0 = -1e30f, mx1 = -1e30f;
#pragma unroll
        for (int j = 0; j < 8; j++) {
            mx0 = fmaxf(mx0, fmaxf(sacc[j][0], sacc[j][1]));
            mx1 = fmaxf(mx1, fmaxf(sacc[j][2], sacc[j][3]));
        }
        mx0 = fmaxf(mx0, __shfl_xor_sync(0xffffffffu, mx0, 1));
        mx0 = fmaxf(mx0, __shfl_xor_sync(0xffffffffu, mx0, 2));
        mx1 = fmaxf(mx1, __shfl_xor_sync(0xffffffffu, mx1, 1));
        mx1 = fmaxf(mx1, __shfl_xor_sync(0xffffffffu, mx1, 2));

        float mn0 = fmaxf(m0, mx0);
        float mn1 = fmaxf(m1, mx1);
        float sc0 = __expf(m0 - mn0);
        float sc1 = __expf(m1 - mn1);
        m0 = mn0;
        m1 = mn1;

        unsigned ph[8][2];
        float rs0 = 0.f, rs1 = 0.f;
#pragma unroll
        for (int j = 0; j < 8; j++) {
            float p00 = __expf(sacc[j][0] - m0);
            float p01 = __expf(sacc[j][1] - m0);
            float p10 = __expf(sacc[j][2] - m1);
            float p11 = __expf(sacc[j][3] - m1);
            rs0 += p00 + p01;
            rs1 += p10 + p11;
            __half2 h0 = __floats2half2_rn(p00, p01);
            __half2 h1 = __floats2half2_rn(p10, p11);
            ph[j][0] = *reinterpret_cast<unsigned*>(&h0);
            ph[j][1] = *reinterpret_cast<unsigned*>(&h1);
        }
        rs0 += __shfl_xor_sync(0xffffffffu, rs0, 1);
        rs0 += __shfl_xor_sync(0xffffffffu, rs0, 2);
        rs1 += __shfl_xor_sync(0xffffffffu, rs1, 1);
        rs1 += __shfl_xor_sync(0xffffffffu, rs1, 2);
        l0 = l0 * sc0 + rs0;
        l1 = l1 * sc1 + rs1;

#pragma unroll
        for (int j = 0; j < 16; j++) {
            oacc[j][0] *= sc0;
            oacc[j][1] *= sc0;
            oacc[j][2] *= sc1;
            oacc[j][3] *= sc1;
        }

        // ---- O += P V ----
#pragma unroll
        for (int c = 0; c < 4; c++) {
            unsigned pa[4];
            pa[0] = ph[2 * c][0];
            pa[1] = ph[2 * c][1];
            pa[2] = ph[2 * c + 1][0];
            pa[3] = ph[2 * c + 1][1];
#pragma unroll
            for (int j = 0; j < 8; j++) {
                unsigned bfr[4];
                ldm_x4_t(bfr, &Vs[(c * 16 + ((lane >> 3) & 1) * 8 + (lane & 7)) * QP + j * 16 + (lane >> 4) * 8]);
                mma16816(oacc[2 * j], pa, bfr[0], bfr[1]);
                mma16816(oacc[2 * j + 1], pa, bfr[2], bfr[3]);
            }
        }
        __syncthreads();
    }

    float sh = sinks[h];
    float mf0 = fmaxf(m0, sh);
    float mf1 = fmaxf(m1, sh);
    float lf0 = l0 * __expf(m0 - mf0) + __expf(sh - mf0);
    float lf1 = l1 * __expf(m1 - mf1) + __expf(sh - mf1);
    float fs0 = __expf(m0 - mf0) / lf0;
    float fs1 = __expf(m1 - mf1) / lf1;

    __half* ob = (__half*)g_h_attn;
    size_t base0 = ((size_t)b * S_ + row0) * QN_ + h * HD_ + (lane & 3) * 2;
    size_t base1 = ((size_t)b * S_ + row1) * QN_ + h * HD_ + (lane & 3) * 2;
#pragma unroll
    for (int j = 0; j < 16; j++) {
        __half2 w0 = __floats2half2_rn(oacc[j][0] * fs0, oacc[j][1] * fs0);
        __half2 w1 = __floats2half2_rn(oacc[j][2] * fs1, oacc[j][3] * fs1);
        *(__half2*)&ob[base0 + j * 8] = w0;
        *(__half2*)&ob[base1 + j * 8] = w1;
    }
}

// ---------------- launch ----------------
extern "C" void kernel_launch(void* const* d_in, const int* in_sizes, int n_in,
                              void* d_out, int out_size)
{
    const float* hidden = (const float*)d_in[0];
    const float* wq = (const float*)d_in[1];
    const float* wkv = (const float*)d_in[2];
    const float* wgate = (const float*)d_in[3];
    const float* ape = (const float*)d_in[4];
    const float* sinks = (const float*)d_in[5];
    const float* wo = (const float*)d_in[6];
    float* out = (float*)d_out;

    void* p_hh = 0;
    void* p_hwf = 0;
    void* p_hwo = 0;
    void* p_hattn = 0;
    cudaGetSymbolAddress(&p_hh, g_h_hidden);
    cudaGetSymbolAddress(&p_hwf, g_h_wfused);
    cudaGetSymbolAddress(&p_hwo, g_h_wo);
    cudaGetSymbolAddress(&p_hattn, g_h_attn);

    init_invfreq_kernel<<<1, 32>>>();

    int n4a = (int)((size_t)MS_ * HID_ / 4);
    f2h_kernel<<<(n4a + 255) / 256, 256>>>((const float4*)hidden, (__half2*)p_hh, n4a);

    int npack = HID_ * QKVN;
    pack_w_kernel<<<(npack + 255) / 256, 256>>>(wq, wkv, wgate, (__half*)p_hwf);

    int n4d = (int)((size_t)QN_ * HID_ / 4);
    f2h_kernel<<<(n4d + 255) / 256, 256>>>((const float4*)wo, (__half2*)p_hwo, n4d);

    cudaFuncSetAttribute(hgemm, cudaFuncAttributeMaxDynamicSharedMemorySize, HG_SMEM);
    cudaFuncSetAttribute(hgemm_qkv, cudaFuncAttributeMaxDynamicSharedMemorySize, HG_SMEM);

    // fused q|kv|gate projection with in-epilogue Q-RoPE
    hgemm_qkv<<<dim3(QKVN / GBN, MS_ / GBM), 256, HG_SMEM>>>(
        (const __half*)p_hh, (const __half*)p_hwf, HID_);

    pool_kernel<<<(B_ * NW_ * 64 + 255) / 256, 256>>>(ape);

    cudaFuncSetAttribute(attn_mma_kernel, cudaFuncAttributeMaxDynamicSharedMemorySize, AT_SMEM);
    attn_mma_kernel<<<dim3(S_ / AQ, NH_, B_), 256, AT_SMEM>>>(sinks);

    hgemm<<<dim3(HID_ / GBN, MS_ / GBM), 256, HG_SMEM>>>(
        (const __half*)p_hattn, (const __half*)p_hwo, out, MS_, HID_, QN_);
}

// round 16
// speedup vs baseline: 1.0069x; 1.0069x over previous
#include <cuda_runtime.h>
#include <cuda_fp16.h>
#include <math.h>

#define B_     2
#define S_     4096
#define HID_   2048
#define NH_    16
#define HD_    128
#define RATIO_ 4
#define NW_    1024
#define MS_    8192
#define QN_    2048
#define QKVN   2560   /* fused q(2048) | kv(256) | gate(256) */
#define KVGN   512

#define AQ  128
#define AK  64
#define QP  136

#define GBM 128
#define GBN 128
#define GBK 64
#define ASTR 72
#define BSTR 136
#define ASTAGE (GBM * ASTR)   /* 9216 halfs */
#define BSTAGE (GBK * BSTR)   /* 8704 halfs */
#define NSTAGE 2
#define HG_SMEM ((NSTAGE * (ASTAGE + BSTAGE)) * 2)   /* 71680 B */

/* attention smem: Q[AQ][QP] + K[2][AK][QP] + V[2][AK][QP] */
#define AT_SMEM ((AQ * QP + 4 * AK * QP) * 2)

// ---------------- scratch (static device allocations) ----------------
__device__ float g_kvg[(size_t)MS_ * KVGN];
__device__ float g_invfreq[32];

__device__ unsigned short g_h_hidden[(size_t)MS_ * HID_];
__device__ unsigned short g_h_wfused[(size_t)HID_ * QKVN];
__device__ unsigned short g_h_wo[(size_t)QN_ * HID_];
__device__ unsigned short g_h_attn[(size_t)MS_ * QN_];
__device__ unsigned short g_h_qrot[(size_t)MS_ * QN_];
__device__ unsigned short g_h_krot[(size_t)B_ * NW_ * HD_];
__device__ unsigned short g_h_v[(size_t)B_ * NW_ * HD_];

// ---------------- one-time inv-freq table ----------------
__global__ void init_invfreq_kernel()
{
    int i = threadIdx.x;
    if (i < 32) {
        g_invfreq[i] = (float)pow(10000.0, -(double)i / 32.0);
    }
}

// ---------------- fp32 -> fp16 (plain) ----------------
__global__ void f2h_kernel(const float4* __restrict__ in, __half2* __restrict__ out, int n4)
{
    int i = blockIdx.x * blockDim.x + threadIdx.x;
    if (i < n4) {
        float4 v = in[i];
        out[2 * i] = __floats2half2_rn(v.x, v.y);
        out[2 * i + 1] = __floats2half2_rn(v.z, v.w);
    }
}

// ---------------- pack wq|wkv|wgate -> fp16 [HID][QKVN] ----------------
__global__ void pack_w_kernel(const float* __restrict__ wq, const float* __restrict__ wkv,
                              const float* __restrict__ wgate, __half* __restrict__ dst)
{
    int idx = blockIdx.x * blockDim.x + threadIdx.x;
    if (idx >= HID_ * QKVN) return;
    int k = idx / QKVN;
    int n = idx % QKVN;
    float v;
    if (n < QN_) {
        v = wq[(size_t)k * QN_ + n];
    } else if (n < QN_ + 256) {
        v = wkv[(size_t)k * 256 + (n - QN_)];
    } else {
        v = wgate[(size_t)k * 256 + (n - QN_ - 256)];
    }
    dst[idx] = __float2half(v);
}

// ---------------- PTX helpers ----------------
__device__ __forceinline__ unsigned su32(const void* p)
{
    return (unsigned)__cvta_generic_to_shared(p);
}

__device__ __forceinline__ void cp16(void* dst, const void* src)
{
    unsigned d = su32(dst);
    asm volatile("cp.async.cg.shared.global [%0], [%1], 16;" :: "r"(d), "l"(src));
}

__device__ __forceinline__ void cp_commit()
{
    asm volatile("cp.async.commit_group;");
}

__device__ __forceinline__ void cp_wait0()
{
    asm volatile("cp.async.wait_group 0;");
}

__device__ __forceinline__ void ldm_x4(unsigned* r, const void* p)
{
    unsigned a = su32(p);
    asm volatile("ldmatrix.sync.aligned.m8n8.x4.shared.b16 {%0,%1,%2,%3}, [%4];"
                 : "=r"(r[0]), "=r"(r[1]), "=r"(r[2]), "=r"(r[3]) : "r"(a));
}

__device__ __forceinline__ void ldm_x4_t(unsigned* r, const void* p)
{
    unsigned a = su32(p);
    asm volatile("ldmatrix.sync.aligned.m8n8.x4.trans.shared.b16 {%0,%1,%2,%3}, [%4];"
                 : "=r"(r[0]), "=r"(r[1]), "=r"(r[2]), "=r"(r[3]) : "r"(a));
}

__device__ __forceinline__ void mma16816(float* c, const unsigned* a, unsigned b0, unsigned b1)
{
    asm volatile("mma.sync.aligned.m16n8k16.row.col.f32.f16.f16.f32 "
                 "{%0,%1,%2,%3},{%4,%5,%6,%7},{%8,%9},{%0,%1,%2,%3};"
                 : "+f"(c[0]), "+f"(c[1]), "+f"(c[2]), "+f"(c[3])
                 : "r"(a[0]), "r"(a[1]), "r"(a[2]), "r"(a[3]), "r"(b0), "r"(b1));
}

// ---------------- GEMM mainloop: 256 threads, 8 warps of 32x64, GBK=64, 2-stage ----------------
struct GemmAcc {
    float a[2][8][4];
};

__device__ __forceinline__ void gemm_mainloop(
    const __half* __restrict__ A, const __half* __restrict__ Bm,
    int N, int K, int rowBase, int colBase, __half* hsm, GemmAcc& R)
{
    __half* As = hsm;
    __half* Bs = hsm + NSTAGE * ASTAGE;

    int tid = threadIdx.x;
    int lane = tid & 31;
    int wid = tid >> 5;
    int warpM = wid & 3;
    int warpN = wid >> 2;

#pragma unroll
    for (int i = 0; i < 2; i++)
#pragma unroll
        for (int j = 0; j < 8; j++)
#pragma unroll
            for (int c = 0; c < 4; c++)
                R.a[i][j][c] = 0.f;

    int T = K / GBK;

    // prologue: stage 0
#pragma unroll
    for (int u = 0; u < 4; u++) {
        int c = tid + u * 256;
        int ar = c >> 3, ac = (c & 7) * 8;
        cp16(&As[ar * ASTR + ac], A + (size_t)(rowBase + ar) * K + ac);
        int br = c >> 4, bc = (c & 15) * 8;
        cp16(&Bs[br * BSTR + bc], Bm + (size_t)br * N + colBase + bc);
    }
    cp_commit();

    for (int t = 0; t < T; t++) {
        cp_wait0();
        __syncthreads();

        if (t + 1 < T) {
            int so = (t + 1) & 1;
            const __half* Ag = A + (size_t)(t + 1) * GBK;
            const __half* Bg = Bm + (size_t)(t + 1) * GBK * N;
#pragma unroll
            for (int u = 0; u < 4; u++) {
                int c = tid + u * 256;
                int ar = c >> 3, ac = (c & 7) * 8;
                cp16(&As[so * ASTAGE + ar * ASTR + ac], Ag + (size_t)(rowBase + ar) * K + ac);
                int br = c >> 4, bc = (c & 15) * 8;
                cp16(&Bs[so * BSTAGE + br * BSTR + bc], Bg + (size_t)br * N + colBase + bc);
            }
            cp_commit();
        }

        int s = t & 1;
        const __half* Asb = &As[s * ASTAGE];
        const __half* Bsb = &Bs[s * BSTAGE];
#pragma unroll
        for (int kk = 0; kk < GBK; kk += 16) {
            unsigned afr[2][4];
            unsigned bfr[4][4];
#pragma unroll
            for (int i = 0; i < 2; i++) {
                ldm_x4(afr[i], &Asb[(warpM * 32 + i * 16 + (lane & 15)) * ASTR + kk + (lane >> 4) * 8]);
            }
#pragma unroll
            for (int j = 0; j < 4; j++) {
                ldm_x4_t(bfr[j], &Bsb[(kk + ((lane >> 3) & 1) * 8 + (lane & 7)) * BSTR + warpN * 64 + j * 16 + (lane >> 4) * 8]);
            }
#pragma unroll
            for (int i = 0; i < 2; i++) {
#pragma unroll
                for (int j = 0; j < 4; j++) {
                    mma16816(R.a[i][2 * j], afr[i], bfr[j][0], bfr[j][1]);
                    mma16816(R.a[i][2 * j + 1], afr[i], bfr[j][2], bfr[j][3]);
                }
            }
        }
        __syncthreads();
    }
}

// ---------------- generic hgemm (fp32 C) for out-projection ----------------
__global__ __launch_bounds__(256, 2) void hgemm(
    const __half* __restrict__ A, const __half* __restrict__ Bm,
    float* __restrict__ C, int M, int N, int K)
{
    extern __shared__ __half hsm[];
    int lane = threadIdx.x & 31;
    int wid = threadIdx.x >> 5;
    int rowBase = blockIdx.y * GBM;
    int colBase = blockIdx.x * GBN;

    GemmAcc R;
    gemm_mainloop(A, Bm, N, K, rowBase, colBase, hsm, R);

    int r0 = rowBase + (wid & 3) * 32 + (lane >> 2);
    int c0 = colBase + (wid >> 2) * 64 + (lane & 3) * 2;
#pragma unroll
    for (int i = 0; i < 2; i++) {
#pragma unroll
        for (int j = 0; j < 8; j++) {
            float2* p0 = (float2*)&C[(size_t)(r0 + i * 16) * N + c0 + j * 8];
            p0[0] = make_float2(R.a[i][j][0], R.a[i][j][1]);
            float2* p1 = (float2*)&C[(size_t)(r0 + i * 16 + 8) * N + c0 + j * 8];
            p1[0] = make_float2(R.a[i][j][2], R.a[i][j][3]);
        }
    }
}

// ---------------- QKV hgemm with fused Q-RoPE epilogue ----------------
__device__ __forceinline__ void write_q_rope(int row, int col, float x, float y)
{
    int b = row >> 12;          // / S_
    int s = row & (S_ - 1);
    int h = col >> 7;           // / HD_
    int d = col & (HD_ - 1);
    int p = d >> 1;
    float y0 = x;
    float y1 = y;
    if (p >= 32) {
        float inv = g_invfreq[p - 32];
        float ang = (float)s * inv;
        float sn, cs;
        sincosf(ang, &sn, &cs);
        y0 = x * cs - y * sn;
        y1 = x * sn + y * cs;
    }
    const float scale = 0.08838834764831845f;
    __half2* dst = (__half2*)((__half*)g_h_qrot + (((size_t)b * NH_ + h) * S_ + s) * HD_ + d);
    dst[0] = __floats2half2_rn(y0 * scale, y1 * scale);
}

__global__ __launch_bounds__(256, 2) void hgemm_qkv(
    const __half* __restrict__ A, const __half* __restrict__ Bm, int K)
{
    extern __shared__ __half hsm[];
    int lane = threadIdx.x & 31;
    int wid = threadIdx.x >> 5;
    int rowBase = blockIdx.y * GBM;
    int colBase = blockIdx.x * GBN;

    GemmAcc R;
    gemm_mainloop(A, Bm, QKVN, K, rowBase, colBase, hsm, R);

    int r0 = rowBase + (wid & 3) * 32 + (lane >> 2);
    int c0 = colBase + (wid >> 2) * 64 + (lane & 3) * 2;

    if (colBase < QN_) {
#pragma unroll
        for (int i = 0; i < 2; i++) {
#pragma unroll
            for (int j = 0; j < 8; j++) {
                int col = c0 + j * 8;
                write_q_rope(r0 + i * 16, col, R.a[i][j][0], R.a[i][j][1]);
                write_q_rope(r0 + i * 16 + 8, col, R.a[i][j][2], R.a[i][j][3]);
            }
        }
    } else {
        int cb = c0 - QN_;
#pragma unroll
        for (int i = 0; i < 2; i++) {
#pragma unroll
            for (int j = 0; j < 8; j++) {
                float2* p0 = (float2*)&g_kvg[(size_t)(r0 + i * 16) * KVGN + cb + j * 8];
                p0[0] = make_float2(R.a[i][j][0], R.a[i][j][1]);
                float2* p1 = (float2*)&g_kvg[(size_t)(r0 + i * 16 + 8) * KVGN + cb + j * 8];
                p1[0] = make_float2(R.a[i][j][2], R.a[i][j][3]);
            }
        }
    }
}

// ---------------- overlap-pool + K-RoPE (reads slim kvg buffer) ----------------
__global__ void pool_kernel(const float* __restrict__ ape)
{
    int idx = blockIdx.x * blockDim.x + threadIdx.x;
    if (idx >= B_ * NW_ * 64) return;
    int p = idx & 63;
    int w = (idx >> 6) % NW_;
    int b = idx / (64 * NW_);
    int d0 = 2 * p;

    const float* base = g_kvg + (size_t)b * S_ * KVGN;

    float kvv[8][2];
    float gv[8][2];
#pragma unroll
    for (int j = 0; j < RATIO_; j++) {
        if (w > 0) {
            int t = (w - 1) * RATIO_ + j;
            const float* rowp = base + (size_t)t * KVGN;
            float2 kk = *(const float2*)&rowp[d0];
            float2 gg = *(const float2*)&rowp[256 + d0];
            float2 aa = *(const float2*)&ape[(size_t)j * 2 * HD_ + d0];
            kvv[j][0] = kk.x;
            kvv[j][1] = kk.y;
            gv[j][0] = gg.x + aa.x;
            gv[j][1] = gg.y + aa.y;
        } else {
            kvv[j][0] = 0.f;
            kvv[j][1] = 0.f;
            gv[j][0] = -1e30f;
            gv[j][1] = -1e30f;
        }
        int t2 = w * RATIO_ + j;
        const float* rowp2 = base + (size_t)t2 * KVGN;
        float2 kk2 = *(const float2*)&rowp2[HD_ + d0];
        float2 gg2 = *(const float2*)&rowp2[256 + HD_ + d0];
        float2 aa2 = *(const float2*)&ape[(size_t)j * 2 * HD_ + HD_ + d0];
        kvv[4 + j][0] = kk2.x;
        kvv[4 + j][1] = kk2.y;
        gv[4 + j][0] = gg2.x + aa2.x;
        gv[4 + j][1] = gg2.y + aa2.y;
    }

    float out2[2];
#pragma unroll
    for (int c = 0; c < 2; c++) {
        float m = -1e30f;
#pragma unroll
        for (int j = 0; j < 8; j++) m = fmaxf(m, gv[j][c]);
        float s = 0.f;
        float acc = 0.f;
#pragma unroll
        for (int j = 0; j < 8; j++) {
            float e = __expf(gv[j][c] - m);
            s += e;
            acc += e * kvv[j][c];
        }
        out2[c] = acc / s;
    }

    __half2* vp = (__half2*)((__half*)g_h_v + ((size_t)b * NW_ + w) * HD_ + d0);
    vp[0] = __floats2half2_rn(out2[0], out2[1]);

    float y0 = out2[0];
    float y1 = out2[1];
    if (p >= 32) {
        int i = p - 32;
        float inv = g_invfreq[i];
        float ang = (float)(w * RATIO_) * inv;
        float sn, cs;
        sincosf(ang, &sn, &cs);
        y0 = out2[0] * cs - out2[1] * sn;
        y1 = out2[0] * sn + out2[1] * cs;
    }
    __half2* kp = (__half2*)((__half*)g_h_krot + ((size_t)b * NW_ + w) * HD_ + d0);
    kp[0] = __floats2half2_rn(y0, y1);
}

// ---------------- tensor-core flash attention with sink, pipelined K/V ----------------
// q-block order REVERSED: heaviest (largest q0, most K tiles) CTAs launch first,
// so the final wave holds the lightest CTAs -> shorter tail.
__global__ __launch_bounds__(256, 1) void attn_mma_kernel(const float* __restrict__ sinks)
{
    extern __shared__ __half smh[];
    __half* Qs = smh;                              // [AQ][QP]
    __half* Kb[2];
    __half* Vb[2];
    Kb[0] = Qs + AQ * QP;
    Vb[0] = Kb[0] + AK * QP;
    Kb[1] = Vb[0] + AK * QP;
    Vb[1] = Kb[1] + AK * QP;

    int tid = threadIdx.x;
    int lane = tid & 31;
    int wid = tid >> 5;
    int b = blockIdx.z;
    int h = blockIdx.y;
    int q0 = (gridDim.x - 1 - blockIdx.x) * AQ;   // reversed scheduling

    // load Q tile
    const __half* qsrc = (const __half*)g_h_qrot + (((size_t)b * NH_ + h) * S_ + q0) * HD_;
#pragma unroll
    for (int t = 0; t < 8; t++) {
        int lin = tid + t * 256;
        int row = lin >> 4;
        int c8 = (lin & 15) * 8;
        *(uint4*)&Qs[row * QP + c8] = *(const uint4*)&qsrc[(size_t)row * HD_ + c8];
    }
    __syncthreads();

    // preload Q fragments into registers (8 k16-chunks)
    unsigned qfr[8][4];
#pragma unroll
    for (int kk8 = 0; kk8 < 8; kk8++) {
        ldm_x4(qfr[kk8], &Qs[(wid * 16 + (lane & 15)) * QP + kk8 * 16 + (lane >> 4) * 8]);
    }

    float m0 = -1e30f, m1 = -1e30f;
    float l0 = 0.f, l1 = 0.f;
    float oacc[16][4];
#pragma unroll
    for (int j = 0; j < 16; j++)
#pragma unroll
        for (int c = 0; c < 4; c++)
            oacc[j][c] = 0.f;

    int kmax = (q0 + AQ - 4) >> 2;
    if (kmax > NW_ - 1) kmax = NW_ - 1;
    int nkt = kmax / AK + 1;

    const __half* kb = (const __half*)g_h_krot + (size_t)b * NW_ * HD_;
    const __half* vb = (const __half*)g_h_v + (size_t)b * NW_ * HD_;

    int row0 = q0 + wid * 16 + (lane >> 2);
    int row1 = row0 + 8;

    int ldrow = tid >> 4;          // 0..15
    int ldc8 = (tid & 15) * 8;

    // prologue: tile 0 -> buf 0
#pragma unroll
    for (int t = 0; t < 4; t++) {
        int row = ldrow + t * 16;
        cp16(&Kb[0][row * QP + ldc8], &kb[(size_t)row * HD_ + ldc8]);
        cp16(&Vb[0][row * QP + ldc8], &vb[(size_t)row * HD_ + ldc8]);
    }
    cp_commit();

    for (int kt = 0; kt < nkt; kt++) {
        cp_wait0();
        __syncthreads();

        if (kt + 1 < nkt) {
            int so = (kt + 1) & 1;
            const __half* kn = kb + (size_t)(kt + 1) * AK * HD_;
            const __half* vn = vb + (size_t)(kt + 1) * AK * HD_;
#pragma unroll
            for (int t = 0; t < 4; t++) {
                int row = ldrow + t * 16;
                cp16(&Kb[so][row * QP + ldc8], &kn[(size_t)row * HD_ + ldc8]);
                cp16(&Vb[so][row * QP + ldc8], &vn[(size_t)row * HD_ + ldc8]);
            }
            cp_commit();
        }

        const __half* Ks = Kb[kt & 1];
        const __half* Vs = Vb[kt & 1];

        // ---- S = Q K^T ----
        float sacc[8][4];
#pragma unroll
        for (int j = 0; j < 8; j++)
#pragma unroll
            for (int c = 0; c < 4; c++)
                sacc[j][c] = 0.f;

#pragma unroll
        for (int kk8 = 0; kk8 < 8; kk8++) {
#pragma unroll
            for (int j = 0; j < 4; j++) {
                unsigned bfr[4];
                ldm_x4(bfr, &Ks[(j * 16 + (lane >> 4) * 8 + (lane & 7)) * QP + kk8 * 16 + ((lane >> 3) & 1) * 8]);
                mma16816(sacc[2 * j], qfr[kk8], bfr[0], bfr[1]);
                mma16816(sacc[2 * j + 1], qfr[kk8], bfr[2], bfr[3]);
            }
        }

        // ---- mask ----
#pragma unroll
        for (int j = 0; j < 8; j++) {
            int kg = kt * AK + j * 8 + (lane & 3) * 2;
            if (row0 < 4 * kg + 3) sacc[j][0] = -1e30f;
            if (row0 < 4 * kg + 7) sacc[j][1] = -1e30f;
            if (row1 < 4 * kg + 3) sacc[j][2] = -1e30f;
            if (row1 < 4 * kg + 7) sacc[j][3] = -1e30f;
        }

        // ---- online softmax ----
        float mx0 = -1e30f, mx1 = -1e30f;
#pragma unroll
        for (int j = 0; j < 8; j++) {
            mx0 = fmaxf(mx0, fmaxf(sacc[j][0], sacc[j][1]));
            mx1 = fmaxf(mx1, fmaxf(sacc[j][2], sacc[j][3]));
        }
        mx0 = fmaxf(mx0, __shfl_xor_sync(0xffffffffu, mx0, 1));
        mx0 = fmaxf(mx0, __shfl_xor_sync(0xffffffffu, mx0, 2));
        mx1 = fmaxf(mx1, __shfl_xor_sync(0xffffffffu, mx1, 1));
        mx1 = fmaxf(mx1, __shfl_xor_sync(0xffffffffu, mx1, 2));

        float mn0 = fmaxf(m0, mx0);
        float mn1 = fmaxf(m1, mx1);
        float sc0 = __expf(m0 - mn0);
        float sc1 = __expf(m1 - mn1);
        m0 = mn0;
        m1 = mn1;

        unsigned ph[8][2];
        float rs0 = 0.f, rs1 = 0.f;
#pragma unroll
        for (int j = 0; j < 8; j++) {
            float p00 = __expf(sacc[j][0] - m0);
            float p01 = __expf(sacc[j][1] - m0);
            float p10 = __expf(sacc[j][2] - m1);
            float p11 = __expf(sacc[j][3] - m1);
            rs0 += p00 + p01;
            rs1 += p10 + p11;
            __half2 h0 = __floats2half2_rn(p00, p01);
            __half2 h1 = __floats2half2_rn(p10, p11);
            ph[j][0] = *reinterpret_cast<unsigned*>(&h0);
            ph[j][1] = *reinterpret_cast<unsigned*>(&h1);
        }
        rs0 += __shfl_xor_sync(0xffffffffu, rs0, 1);
        rs0 += __shfl_xor_sync(0xffffffffu, rs0, 2);
        rs1 += __shfl_xor_sync(0xffffffffu, rs1, 1);
        rs1 += __shfl_xor_sync(0xffffffffu, rs1, 2);
        l0 = l0 * sc0 + rs0;
        l1 = l1 * sc1 + rs1;

#pragma unroll
        for (int j = 0; j < 16; j++) {
            oacc[j][0] *= sc0;
            oacc[j][1] *= sc0;
            oacc[j][2] *= sc1;
            oacc[j][3] *= sc1;
        }

        // ---- O += P V ----
#pragma unroll
        for (int c = 0; c < 4; c++) {
            unsigned pa[4];
            pa[0] = ph[2 * c][0];
            pa[1] = ph[2 * c][1];
            pa[2] = ph[2 * c + 1][0];
            pa[3] = ph[2 * c + 1][1];
#pragma unroll
            for (int j = 0; j < 8; j++) {
                unsigned bfr[4];
                ldm_x4_t(bfr, &Vs[(c * 16 + ((lane >> 3) & 1) * 8 + (lane & 7)) * QP + j * 16 + (lane >> 4) * 8]);
                mma16816(oacc[2 * j], pa, bfr[0], bfr[1]);
                mma16816(oacc[2 * j + 1], pa, bfr[2], bfr[3]);
            }
        }
        __syncthreads();
    }

    float sh = sinks[h];
    float mf0 = fmaxf(m0, sh);
    float mf1 = fmaxf(m1, sh);
    float lf0 = l0 * __expf(m0 - mf0) + __expf(sh - mf0);
    float lf1 = l1 * __expf(m1 - mf1) + __expf(sh - mf1);
    float fs0 = __expf(m0 - mf0) / lf0;
    float fs1 = __expf(m1 - mf1) / lf1;

    __half* ob = (__half*)g_h_attn;
    size_t base0 = ((size_t)b * S_ + row0) * QN_ + h * HD_ + (lane & 3) * 2;
    size_t base1 = ((size_t)b * S_ + row1) * QN_ + h * HD_ + (lane & 3) * 2;
#pragma unroll
    for (int j = 0; j < 16; j++) {
        __half2 w0 = __floats2half2_rn(oacc[j][0] * fs0, oacc[j][1] * fs0);
        __half2 w1 = __floats2half2_rn(oacc[j][2] * fs1, oacc[j][3] * fs1);
        *(__half2*)&ob[base0 + j * 8] = w0;
        *(__half2*)&ob[base1 + j * 8] = w1;
    }
}

// ---------------- launch ----------------
extern "C" void kernel_launch(void* const* d_in, const int* in_sizes, int n_in,
                              void* d_out, int out_size)
{
    const float* hidden = (const float*)d_in[0];
    const float* wq = (const float*)d_in[1];
    const float* wkv = (const float*)d_in[2];
    const float* wgate = (const float*)d_in[3];
    const float* ape = (const float*)d_in[4];
    const float* sinks = (const float*)d_in[5];
    const float* wo = (const float*)d_in[6];
    float* out = (float*)d_out;

    void* p_hh = 0;
    void* p_hwf = 0;
    void* p_hwo = 0;
    void* p_hattn = 0;
    cudaGetSymbolAddress(&p_hh, g_h_hidden);
    cudaGetSymbolAddress(&p_hwf, g_h_wfused);
    cudaGetSymbolAddress(&p_hwo, g_h_wo);
    cudaGetSymbolAddress(&p_hattn, g_h_attn);

    init_invfreq_kernel<<<1, 32>>>();

    int n4a = (int)((size_t)MS_ * HID_ / 4);
    f2h_kernel<<<(n4a + 255) / 256, 256>>>((const float4*)hidden, (__half2*)p_hh, n4a);

    int npack = HID_ * QKVN;
    pack_w_kernel<<<(npack + 255) / 256, 256>>>(wq, wkv, wgate, (__half*)p_hwf);

    int n4d = (int)((size_t)QN_ * HID_ / 4);
    f2h_kernel<<<(n4d + 255) / 256, 256>>>((const float4*)wo, (__half2*)p_hwo, n4d);

    cudaFuncSetAttribute(hgemm, cudaFuncAttributeMaxDynamicSharedMemorySize, HG_SMEM);
    cudaFuncSetAttribute(hgemm_qkv, cudaFuncAttributeMaxDynamicSharedMemorySize, HG_SMEM);

    // fused q|kv|gate projection with in-epilogue Q-RoPE
    hgemm_qkv<<<dim3(QKVN / GBN, MS_ / GBM), 256, HG_SMEM>>>(
        (const __half*)p_hh, (const __half*)p_hwf, HID_);

    pool_kernel<<<(B_ * NW_ * 64 + 255) / 256, 256>>>(ape);

    cudaFuncSetAttribute(attn_mma_kernel, cudaFuncAttributeMaxDynamicSharedMemorySize, AT_SMEM);
    attn_mma_kernel<<<dim3(S_ / AQ, NH_, B_), 256, AT_SMEM>>>(sinks);

    hgemm<<<dim3(HID_ / GBN, MS_ / GBM), 256, HG_SMEM>>>(
        (const __half*)p_hattn, (const __half*)p_hwo, out, MS_, HID_, QN_);
}

// round 17
// speedup vs baseline: 1.0240x; 1.0170x over previous
#include <cuda_runtime.h>
#include <cuda_fp16.h>
#include <math.h>

#define B_     2
#define S_     4096
#define HID_   2048
#define NH_    16
#define HD_    128
#define RATIO_ 4
#define NW_    1024
#define MS_    8192
#define QN_    2048
#define QKVN   2560   /* fused q(2048) | kv(256) | gate(256) */
#define KVGN   512

#define AQ  128
#define AK  64
#define QP  136

#define GBM 128
#define GBN 128
#define GBK 64
#define ASTR 72
#define BSTR 136
#define ASTAGE (GBM * ASTR)   /* 9216 halfs */
#define BSTAGE (GBK * BSTR)   /* 8704 halfs */
#define NSTAGE 2
#define HG_SMEM ((NSTAGE * (ASTAGE + BSTAGE)) * 2)   /* 71680 B */

/* attention smem: Q[AQ][QP] + K[2][AK][QP] + V[2][AK][QP] */
#define AT_SMEM ((AQ * QP + 4 * AK * QP) * 2)

// ---------------- scratch (static device allocations) ----------------
__device__ float g_kvg[(size_t)MS_ * KVGN];
__device__ float g_invfreq[32];

__device__ unsigned short g_h_hidden[(size_t)MS_ * HID_];
__device__ unsigned short g_h_wfused[(size_t)HID_ * QKVN];
__device__ unsigned short g_h_wo[(size_t)QN_ * HID_];
__device__ unsigned short g_h_attn[(size_t)MS_ * QN_];
__device__ unsigned short g_h_qrot[(size_t)MS_ * QN_];
__device__ unsigned short g_h_krot[(size_t)B_ * NW_ * HD_];
__device__ unsigned short g_h_v[(size_t)B_ * NW_ * HD_];

// ---------------- one-time inv-freq table ----------------
__global__ void init_invfreq_kernel()
{
    int i = threadIdx.x;
    if (i < 32) {
        g_invfreq[i] = (float)pow(10000.0, -(double)i / 32.0);
    }
}

// ---------------- fp32 -> fp16 with 4-way ILP ----------------
// Each thread: 4 independent float4 loads (MLP=4), 8 half2 stores.
__global__ void f2h_kernel(const float4* __restrict__ in, __half2* __restrict__ out, int n4)
{
    int base = blockIdx.x * (blockDim.x * 4) + threadIdx.x;
    int str = blockDim.x;
    float4 v0, v1, v2, v3;
    bool b0 = base < n4;
    bool b1 = base + str < n4;
    bool b2 = base + 2 * str < n4;
    bool b3 = base + 3 * str < n4;
    if (b0) v0 = in[base];
    if (b1) v1 = in[base + str];
    if (b2) v2 = in[base + 2 * str];
    if (b3) v3 = in[base + 3 * str];
    if (b0) {
        out[2 * base] = __floats2half2_rn(v0.x, v0.y);
        out[2 * base + 1] = __floats2half2_rn(v0.z, v0.w);
    }
    if (b1) {
        int i = base + str;
        out[2 * i] = __floats2half2_rn(v1.x, v1.y);
        out[2 * i + 1] = __floats2half2_rn(v1.z, v1.w);
    }
    if (b2) {
        int i = base + 2 * str;
        out[2 * i] = __floats2half2_rn(v2.x, v2.y);
        out[2 * i + 1] = __floats2half2_rn(v2.z, v2.w);
    }
    if (b3) {
        int i = base + 3 * str;
        out[2 * i] = __floats2half2_rn(v3.x, v3.y);
        out[2 * i + 1] = __floats2half2_rn(v3.z, v3.w);
    }
}

// ---------------- pack wq|wkv|wgate -> fp16 [HID][QKVN], vectorized ----------------
// One float4-group per index; segment boundaries (2048, 2304) are multiples of 4.
__global__ void pack_w_kernel(const float* __restrict__ wq, const float* __restrict__ wkv,
                              const float* __restrict__ wgate, __half* __restrict__ dst)
{
    int idx4 = blockIdx.x * blockDim.x + threadIdx.x;   // HID_*QKVN/4 groups
    if (idx4 >= HID_ * QKVN / 4) return;
    int k = idx4 / (QKVN / 4);
    int n = (idx4 % (QKVN / 4)) * 4;
    float4 v;
    if (n < QN_) {
        v = *(const float4*)&wq[(size_t)k * QN_ + n];
    } else if (n < QN_ + 256) {
        v = *(const float4*)&wkv[(size_t)k * 256 + (n - QN_)];
    } else {
        v = *(const float4*)&wgate[(size_t)k * 256 + (n - QN_ - 256)];
    }
    __half2* d = (__half2*)&dst[(size_t)k * QKVN + n];
    d[0] = __floats2half2_rn(v.x, v.y);
    d[1] = __floats2half2_rn(v.z, v.w);
}

// ---------------- PTX helpers ----------------
__device__ __forceinline__ unsigned su32(const void* p)
{
    return (unsigned)__cvta_generic_to_shared(p);
}

__device__ __forceinline__ void cp16(void* dst, const void* src)
{
    unsigned d = su32(dst);
    asm volatile("cp.async.cg.shared.global [%0], [%1], 16;" :: "r"(d), "l"(src));
}

__device__ __forceinline__ void cp_commit()
{
    asm volatile("cp.async.commit_group;");
}

__device__ __forceinline__ void cp_wait0()
{
    asm volatile("cp.async.wait_group 0;");
}

__device__ __forceinline__ void ldm_x4(unsigned* r, const void* p)
{
    unsigned a = su32(p);
    asm volatile("ldmatrix.sync.aligned.m8n8.x4.shared.b16 {%0,%1,%2,%3}, [%4];"
                 : "=r"(r[0]), "=r"(r[1]), "=r"(r[2]), "=r"(r[3]) : "r"(a));
}

__device__ __forceinline__ void ldm_x4_t(unsigned* r, const void* p)
{
    unsigned a = su32(p);
    asm volatile("ldmatrix.sync.aligned.m8n8.x4.trans.shared.b16 {%0,%1,%2,%3}, [%4];"
                 : "=r"(r[0]), "=r"(r[1]), "=r"(r[2]), "=r"(r[3]) : "r"(a));
}

__device__ __forceinline__ void mma16816(float* c, const unsigned* a, unsigned b0, unsigned b1)
{
    asm volatile("mma.sync.aligned.m16n8k16.row.col.f32.f16.f16.f32 "
                 "{%0,%1,%2,%3},{%4,%5,%6,%7},{%8,%9},{%0,%1,%2,%3};"
                 : "+f"(c[0]), "+f"(c[1]), "+f"(c[2]), "+f"(c[3])
                 : "r"(a[0]), "r"(a[1]), "r"(a[2]), "r"(a[3]), "r"(b0), "r"(b1));
}

// ---------------- GEMM mainloop: 256 threads, 8 warps of 32x64, GBK=64, 2-stage ----------------
struct GemmAcc {
    float a[2][8][4];
};

__device__ __forceinline__ void gemm_mainloop(
    const __half* __restrict__ A, const __half* __restrict__ Bm,
    int N, int K, int rowBase, int colBase, __half* hsm, GemmAcc& R)
{
    __half* As = hsm;
    __half* Bs = hsm + NSTAGE * ASTAGE;

    int tid = threadIdx.x;
    int lane = tid & 31;
    int wid = tid >> 5;
    int warpM = wid & 3;
    int warpN = wid >> 2;

#pragma unroll
    for (int i = 0; i < 2; i++)
#pragma unroll
        for (int j = 0; j < 8; j++)
#pragma unroll
            for (int c = 0; c < 4; c++)
                R.a[i][j][c] = 0.f;

    int T = K / GBK;

    // prologue: stage 0
#pragma unroll
    for (int u = 0; u < 4; u++) {
        int c = tid + u * 256;
        int ar = c >> 3, ac = (c & 7) * 8;
        cp16(&As[ar * ASTR + ac], A + (size_t)(rowBase + ar) * K + ac);
        int br = c >> 4, bc = (c & 15) * 8;
        cp16(&Bs[br * BSTR + bc], Bm + (size_t)br * N + colBase + bc);
    }
    cp_commit();

    for (int t = 0; t < T; t++) {
        cp_wait0();
        __syncthreads();

        if (t + 1 < T) {
            int so = (t + 1) & 1;
            const __half* Ag = A + (size_t)(t + 1) * GBK;
            const __half* Bg = Bm + (size_t)(t + 1) * GBK * N;
#pragma unroll
            for (int u = 0; u < 4; u++) {
                int c = tid + u * 256;
                int ar = c >> 3, ac = (c & 7) * 8;
                cp16(&As[so * ASTAGE + ar * ASTR + ac], Ag + (size_t)(rowBase + ar) * K + ac);
                int br = c >> 4, bc = (c & 15) * 8;
                cp16(&Bs[so * BSTAGE + br * BSTR + bc], Bg + (size_t)br * N + colBase + bc);
            }
            cp_commit();
        }

        int s = t & 1;
        const __half* Asb = &As[s * ASTAGE];
        const __half* Bsb = &Bs[s * BSTAGE];
#pragma unroll
        for (int kk = 0; kk < GBK; kk += 16) {
            unsigned afr[2][4];
            unsigned bfr[4][4];
#pragma unroll
            for (int i = 0; i < 2; i++) {
                ldm_x4(afr[i], &Asb[(warpM * 32 + i * 16 + (lane & 15)) * ASTR + kk + (lane >> 4) * 8]);
            }
#pragma unroll
            for (int j = 0; j < 4; j++) {
                ldm_x4_t(bfr[j], &Bsb[(kk + ((lane >> 3) & 1) * 8 + (lane & 7)) * BSTR + warpN * 64 + j * 16 + (lane >> 4) * 8]);
            }
#pragma unroll
            for (int i = 0; i < 2; i++) {
#pragma unroll
                for (int j = 0; j < 4; j++) {
                    mma16816(R.a[i][2 * j], afr[i], bfr[j][0], bfr[j][1]);
                    mma16816(R.a[i][2 * j + 1], afr[i], bfr[j][2], bfr[j][3]);
                }
            }
        }
        __syncthreads();
    }
}

// ---------------- generic hgemm (fp32 C) for out-projection ----------------
__global__ __launch_bounds__(256, 2) void hgemm(
    const __half* __restrict__ A, const __half* __restrict__ Bm,
    float* __restrict__ C, int M, int N, int K)
{
    extern __shared__ __half hsm[];
    int lane = threadIdx.x & 31;
    int wid = threadIdx.x >> 5;
    int rowBase = blockIdx.y * GBM;
    int colBase = blockIdx.x * GBN;

    GemmAcc R;
    gemm_mainloop(A, Bm, N, K, rowBase, colBase, hsm, R);

    int r0 = rowBase + (wid & 3) * 32 + (lane >> 2);
    int c0 = colBase + (wid >> 2) * 64 + (lane & 3) * 2;
#pragma unroll
    for (int i = 0; i < 2; i++) {
#pragma unroll
        for (int j = 0; j < 8; j++) {
            float2* p0 = (float2*)&C[(size_t)(r0 + i * 16) * N + c0 + j * 8];
            p0[0] = make_float2(R.a[i][j][0], R.a[i][j][1]);
            float2* p1 = (float2*)&C[(size_t)(r0 + i * 16 + 8) * N + c0 + j * 8];
            p1[0] = make_float2(R.a[i][j][2], R.a[i][j][3]);
        }
    }
}

// ---------------- QKV hgemm with fused Q-RoPE epilogue ----------------
__device__ __forceinline__ void write_q_rope(int row, int col, float x, float y)
{
    int b = row >> 12;          // / S_
    int s = row & (S_ - 1);
    int h = col >> 7;           // / HD_
    int d = col & (HD_ - 1);
    int p = d >> 1;
    float y0 = x;
    float y1 = y;
    if (p >= 32) {
        float inv = g_invfreq[p - 32];
        float ang = (float)s * inv;
        float sn, cs;
        sincosf(ang, &sn, &cs);
        y0 = x * cs - y * sn;
        y1 = x * sn + y * cs;
    }
    const float scale = 0.08838834764831845f;
    __half2* dst = (__half2*)((__half*)g_h_qrot + (((size_t)b * NH_ + h) * S_ + s) * HD_ + d);
    dst[0] = __floats2half2_rn(y0 * scale, y1 * scale);
}

__global__ __launch_bounds__(256, 2) void hgemm_qkv(
    const __half* __restrict__ A, const __half* __restrict__ Bm, int K)
{
    extern __shared__ __half hsm[];
    int lane = threadIdx.x & 31;
    int wid = threadIdx.x >> 5;
    int rowBase = blockIdx.y * GBM;
    int colBase = blockIdx.x * GBN;

    GemmAcc R;
    gemm_mainloop(A, Bm, QKVN, K, rowBase, colBase, hsm, R);

    int r0 = rowBase + (wid & 3) * 32 + (lane >> 2);
    int c0 = colBase + (wid >> 2) * 64 + (lane & 3) * 2;

    if (colBase < QN_) {
#pragma unroll
        for (int i = 0; i < 2; i++) {
#pragma unroll
            for (int j = 0; j < 8; j++) {
                int col = c0 + j * 8;
                write_q_rope(r0 + i * 16, col, R.a[i][j][0], R.a[i][j][1]);
                write_q_rope(r0 + i * 16 + 8, col, R.a[i][j][2], R.a[i][j][3]);
            }
        }
    } else {
        int cb = c0 - QN_;
#pragma unroll
        for (int i = 0; i < 2; i++) {
#pragma unroll
            for (int j = 0; j < 8; j++) {
                float2* p0 = (float2*)&g_kvg[(size_t)(r0 + i * 16) * KVGN + cb + j * 8];
                p0[0] = make_float2(R.a[i][j][0], R.a[i][j][1]);
                float2* p1 = (float2*)&g_kvg[(size_t)(r0 + i * 16 + 8) * KVGN + cb + j * 8];
                p1[0] = make_float2(R.a[i][j][2], R.a[i][j][3]);
            }
        }
    }
}

// ---------------- overlap-pool + K-RoPE (reads slim kvg buffer) ----------------
__global__ void pool_kernel(const float* __restrict__ ape)
{
    int idx = blockIdx.x * blockDim.x + threadIdx.x;
    if (idx >= B_ * NW_ * 64) return;
    int p = idx & 63;
    int w = (idx >> 6) % NW_;
    int b = idx / (64 * NW_);
    int d0 = 2 * p;

    const float* base = g_kvg + (size_t)b * S_ * KVGN;

    float kvv[8][2];
    float gv[8][2];
#pragma unroll
    for (int j = 0; j < RATIO_; j++) {
        if (w > 0) {
            int t = (w - 1) * RATIO_ + j;
            const float* rowp = base + (size_t)t * KVGN;
            float2 kk = *(const float2*)&rowp[d0];
            float2 gg = *(const float2*)&rowp[256 + d0];
            float2 aa = *(const float2*)&ape[(size_t)j * 2 * HD_ + d0];
            kvv[j][0] = kk.x;
            kvv[j][1] = kk.y;
            gv[j][0] = gg.x + aa.x;
            gv[j][1] = gg.y + aa.y;
        } else {
            kvv[j][0] = 0.f;
            kvv[j][1] = 0.f;
            gv[j][0] = -1e30f;
            gv[j][1] = -1e30f;
        }
        int t2 = w * RATIO_ + j;
        const float* rowp2 = base + (size_t)t2 * KVGN;
        float2 kk2 = *(const float2*)&rowp2[HD_ + d0];
        float2 gg2 = *(const float2*)&rowp2[256 + HD_ + d0];
        float2 aa2 = *(const float2*)&ape[(size_t)j * 2 * HD_ + HD_ + d0];
        kvv[4 + j][0] = kk2.x;
        kvv[4 + j][1] = kk2.y;
        gv[4 + j][0] = gg2.x + aa2.x;
        gv[4 + j][1] = gg2.y + aa2.y;
    }

    float out2[2];
#pragma unroll
    for (int c = 0; c < 2; c++) {
        float m = -1e30f;
#pragma unroll
        for (int j = 0; j < 8; j++) m = fmaxf(m, gv[j][c]);
        float s = 0.f;
        float acc = 0.f;
#pragma unroll
        for (int j = 0; j < 8; j++) {
            float e = __expf(gv[j][c] - m);
            s += e;
            acc += e * kvv[j][c];
        }
        out2[c] = acc / s;
    }

    __half2* vp = (__half2*)((__half*)g_h_v + ((size_t)b * NW_ + w) * HD_ + d0);
    vp[0] = __floats2half2_rn(out2[0], out2[1]);

    float y0 = out2[0];
    float y1 = out2[1];
    if (p >= 32) {
        int i = p - 32;
        float inv = g_invfreq[i];
        float ang = (float)(w * RATIO_) * inv;
        float sn, cs;
        sincosf(ang, &sn, &cs);
        y0 = out2[0] * cs - out2[1] * sn;
        y1 = out2[0] * sn + out2[1] * cs;
    }
    __half2* kp = (__half2*)((__half*)g_h_krot + ((size_t)b * NW_ + w) * HD_ + d0);
    kp[0] = __floats2half2_rn(y0, y1);
}

// ---------------- tensor-core flash attention with sink, pipelined K/V ----------------
__global__ __launch_bounds__(256, 1) void attn_mma_kernel(const float* __restrict__ sinks)
{
    extern __shared__ __half smh[];
    __half* Qs = smh;                              // [AQ][QP]
    __half* Kb[2];
    __half* Vb[2];
    Kb[0] = Qs + AQ * QP;
    Vb[0] = Kb[0] + AK * QP;
    Kb[1] = Vb[0] + AK * QP;
    Vb[1] = Kb[1] + AK * QP;

    int tid = threadIdx.x;
    int lane = tid & 31;
    int wid = tid >> 5;
    int b = blockIdx.z;
    int h = blockIdx.y;
    int q0 = (gridDim.x - 1 - blockIdx.x) * AQ;   // reversed scheduling

    // load Q tile
    const __half* qsrc = (const __half*)g_h_qrot + (((size_t)b * NH_ + h) * S_ + q0) * HD_;
#pragma unroll
    for (int t = 0; t < 8; t++) {
        int lin = tid + t * 256;
        int row = lin >> 4;
        int c8 = (lin & 15) * 8;
        *(uint4*)&Qs[row * QP + c8] = *(const uint4*)&qsrc[(size_t)row * HD_ + c8];
    }
    __syncthreads();

    // preload Q fragments into registers (8 k16-chunks)
    unsigned qfr[8][4];
#pragma unroll
    for (int kk8 = 0; kk8 < 8; kk8++) {
        ldm_x4(qfr[kk8], &Qs[(wid * 16 + (lane & 15)) * QP + kk8 * 16 + (lane >> 4) * 8]);
    }

    float m0 = -1e30f, m1 = -1e30f;
    float l0 = 0.f, l1 = 0.f;
    float oacc[16][4];
#pragma unroll
    for (int j = 0; j < 16; j++)
#pragma unroll
        for (int c = 0; c < 4; c++)
            oacc[j][c] = 0.f;

    int kmax = (q0 + AQ - 4) >> 2;
    if (kmax > NW_ - 1) kmax = NW_ - 1;
    int nkt = kmax / AK + 1;

    const __half* kb = (const __half*)g_h_krot + (size_t)b * NW_ * HD_;
    const __half* vb = (const __half*)g_h_v + (size_t)b * NW_ * HD_;

    int row0 = q0 + wid * 16 + (lane >> 2);
    int row1 = row0 + 8;

    int ldrow = tid >> 4;          // 0..15
    int ldc8 = (tid & 15) * 8;

    // prologue: tile 0 -> buf 0
#pragma unroll
    for (int t = 0; t < 4; t++) {
        int row = ldrow + t * 16;
        cp16(&Kb[0][row * QP + ldc8], &kb[(size_t)row * HD_ + ldc8]);
        cp16(&Vb[0][row * QP + ldc8], &vb[(size_t)row * HD_ + ldc8]);
    }
    cp_commit();

    for (int kt = 0; kt < nkt; kt++) {
        cp_wait0();
        __syncthreads();

        if (kt + 1 < nkt) {
            int so = (kt + 1) & 1;
            const __half* kn = kb + (size_t)(kt + 1) * AK * HD_;
            const __half* vn = vb + (size_t)(kt + 1) * AK * HD_;
#pragma unroll
            for (int t = 0; t < 4; t++) {
                int row = ldrow + t * 16;
                cp16(&Kb[so][row * QP + ldc8], &kn[(size_t)row * HD_ + ldc8]);
                cp16(&Vb[so][row * QP + ldc8], &vn[(size_t)row * HD_ + ldc8]);
            }
            cp_commit();
        }

        const __half* Ks = Kb[kt & 1];
        const __half* Vs = Vb[kt & 1];

        // ---- S = Q K^T ----
        float sacc[8][4];
#pragma unroll
        for (int j = 0; j < 8; j++)
#pragma unroll
            for (int c = 0; c < 4; c++)
                sacc[j][c] = 0.f;

#pragma unroll
        for (int kk8 = 0; kk8 < 8; kk8++) {
#pragma unroll
            for (int j = 0; j < 4; j++) {
                unsigned bfr[4];
                ldm_x4(bfr, &Ks[(j * 16 + (lane >> 4) * 8 + (lane & 7)) * QP + kk8 * 16 + ((lane >> 3) & 1) * 8]);
                mma16816(sacc[2 * j], qfr[kk8], bfr[0], bfr[1]);
                mma16816(sacc[2 * j + 1], qfr[kk8], bfr[2], bfr[3]);
            }
        }

        // ---- mask ----
#pragma unroll
        for (int j = 0; j < 8; j++) {
            int kg = kt * AK + j * 8 + (lane & 3) * 2;
            if (row0 < 4 * kg + 3) sacc[j][0] = -1e30f;
            if (row0 < 4 * kg + 7) sacc[j][1] = -1e30f;
            if (row1 < 4 * kg + 3) sacc[j][2] = -1e30f;
            if (row1 < 4 * kg + 7) sacc[j][3] = -1e30f;
        }

        // ---- online softmax ----
        float mx0 = -1e30f, mx1 = -1e30f;
#pragma unroll
        for (int j = 0; j < 8; j++) {
            mx0 = fmaxf(mx0, fmaxf(sacc[j][0], sacc[j][1]));
            mx1 = fmaxf(mx1, fmaxf(sacc[j][2], sacc[j][3]));
        }
        mx0 = fmaxf(mx0, __shfl_xor_sync(0xffffffffu, mx0, 1));
        mx0 = fmaxf(mx0, __shfl_xor_sync(0xffffffffu, mx0, 2));
        mx1 = fmaxf(mx1, __shfl_xor_sync(0xffffffffu, mx1, 1));
        mx1 = fmaxf(mx1, __shfl_xor_sync(0xffffffffu, mx1, 2));

        float mn0 = fmaxf(m0, mx0);
        float mn1 = fmaxf(m1, mx1);
        float sc0 = __expf(m0 - mn0);
        float sc1 = __expf(m1 - mn1);
        m0 = mn0;
        m1 = mn1;

        unsigned ph[8][2];
        float rs0 = 0.f, rs1 = 0.f;
#pragma unroll
        for (int j = 0; j < 8; j++) {
            float p00 = __expf(sacc[j][0] - m0);
            float p01 = __expf(sacc[j][1] - m0);
            float p10 = __expf(sacc[j][2] - m1);
            float p11 = __expf(sacc[j][3] - m1);
            rs0 += p00 + p01;
            rs1 += p10 + p11;
            __half2 h0 = __floats2half2_rn(p00, p01);
            __half2 h1 = __floats2half2_rn(p10, p11);
            ph[j][0] = *reinterpret_cast<unsigned*>(&h0);
            ph[j][1] = *reinterpret_cast<unsigned*>(&h1);
        }
        rs0 += __shfl_xor_sync(0xffffffffu, rs0, 1);
        rs0 += __shfl_xor_sync(0xffffffffu, rs0, 2);
        rs1 += __shfl_xor_sync(0xffffffffu, rs1, 1);
        rs1 += __shfl_xor_sync(0xffffffffu, rs1, 2);
        l0 = l0 * sc0 + rs0;
        l1 = l1 * sc1 + rs1;

#pragma unroll
        for (int j = 0; j < 16; j++) {
            oacc[j][0] *= sc0;
            oacc[j][1] *= sc0;
            oacc[j][2] *= sc1;
            oacc[j][3] *= sc1;
        }

        // ---- O += P V ----
#pragma unroll
        for (int c = 0; c < 4; c++) {
            unsigned pa[4];
            pa[0] = ph[2 * c][0];
            pa[1] = ph[2 * c][1];
            pa[2] = ph[2 * c + 1][0];
            pa[3] = ph[2 * c + 1][1];
#pragma unroll
            for (int j = 0; j < 8; j++) {
                unsigned bfr[4];
                ldm_x4_t(bfr, &Vs[(c * 16 + ((lane >> 3) & 1) * 8 + (lane & 7)) * QP + j * 16 + (lane >> 4) * 8]);
                mma16816(oacc[2 * j], pa, bfr[0], bfr[1]);
                mma16816(oacc[2 * j + 1], pa, bfr[2], bfr[3]);
            }
        }
        __syncthreads();
    }

    float sh = sinks[h];
    float mf0 = fmaxf(m0, sh);
    float mf1 = fmaxf(m1, sh);
    float lf0 = l0 * __expf(m0 - mf0) + __expf(sh - mf0);
    float lf1 = l1 * __expf(m1 - mf1) + __expf(sh - mf1);
    float fs0 = __expf(m0 - mf0) / lf0;
    float fs1 = __expf(m1 - mf1) / lf1;

    __half* ob = (__half*)g_h_attn;
    size_t base0 = ((size_t)b * S_ + row0) * QN_ + h * HD_ + (lane & 3) * 2;
    size_t base1 = ((size_t)b * S_ + row1) * QN_ + h * HD_ + (lane & 3) * 2;
#pragma unroll
    for (int j = 0; j < 16; j++) {
        __half2 w0 = __floats2half2_rn(oacc[j][0] * fs0, oacc[j][1] * fs0);
        __half2 w1 = __floats2half2_rn(oacc[j][2] * fs1, oacc[j][3] * fs1);
        *(__half2*)&ob[base0 + j * 8] = w0;
        *(__half2*)&ob[base1 + j * 8] = w1;
    }
}

// ---------------- launch ----------------
extern "C" void kernel_launch(void* const* d_in, const int* in_sizes, int n_in,
                              void* d_out, int out_size)
{
    const float* hidden = (const float*)d_in[0];
    const float* wq = (const float*)d_in[1];
    const float* wkv = (const float*)d_in[2];
    const float* wgate = (const float*)d_in[3];
    const float* ape = (const float*)d_in[4];
    const float* sinks = (const float*)d_in[5];
    const float* wo = (const float*)d_in[6];
    float* out = (float*)d_out;

    void* p_hh = 0;
    void* p_hwf = 0;
    void* p_hwo = 0;
    void* p_hattn = 0;
    cudaGetSymbolAddress(&p_hh, g_h_hidden);
    cudaGetSymbolAddress(&p_hwf, g_h_wfused);
    cudaGetSymbolAddress(&p_hwo, g_h_wo);
    cudaGetSymbolAddress(&p_hattn, g_h_attn);

    init_invfreq_kernel<<<1, 32>>>();

    int n4a = (int)((size_t)MS_ * HID_ / 4);
    f2h_kernel<<<(n4a + 1023) / 1024, 256>>>((const float4*)hidden, (__half2*)p_hh, n4a);

    int ngrp = HID_ * QKVN / 4;
    pack_w_kernel<<<(ngrp + 255) / 256, 256>>>(wq, wkv, wgate, (__half*)p_hwf);

    int n4d = (int)((size_t)QN_ * HID_ / 4);
    f2h_kernel<<<(n4d + 1023) / 1024, 256>>>((const float4*)wo, (__half2*)p_hwo, n4d);

    cudaFuncSetAttribute(hgemm, cudaFuncAttributeMaxDynamicSharedMemorySize, HG_SMEM);
    cudaFuncSetAttribute(hgemm_qkv, cudaFuncAttributeMaxDynamicSharedMemorySize, HG_SMEM);

    // fused q|kv|gate projection with in-epilogue Q-RoPE
    hgemm_qkv<<<dim3(QKVN / GBN, MS_ / GBM), 256, HG_SMEM>>>(
        (const __half*)p_hh, (const __half*)p_hwf, HID_);

    pool_kernel<<<(B_ * NW_ * 64 + 255) / 256, 256>>>(ape);

    cudaFuncSetAttribute(attn_mma_kernel, cudaFuncAttributeMaxDynamicSharedMemorySize, AT_SMEM);
    attn_mma_kernel<<<dim3(S_ / AQ, NH_, B_), 256, AT_SMEM>>>(sinks);

    hgemm<<<dim3(HID_ / GBN, MS_ / GBM), 256, HG_SMEM>>>(
        (const __half*)p_hattn, (const __half*)p_hwo, out, MS_, HID_, QN_);
}